// round 5
// baseline (speedup 1.0000x reference)
#include <cuda_runtime.h>

// GCBFSafetyLayer — final kernel.
//
// Algebraic reduction: L_g_h = dh_dx @ g is identically zero. dh_dx's nonzero
// state columns (position jacobian, cols 0..1) meet only g's zero rows (0..1);
// g's I/MASS rows (2..3) meet dh_dx's zero columns (2..3). In project(),
// an = ||a||^2 = 0 fails the (an > 1e-6) gate for every constraint on every
// iteration, so u is never modified and safe_action == raw_action BIT-EXACT
// (rel_err = 0.0 measured). Kernel = copy d_in[3] (B*N*P = 65536 f32
// = 16384 float4) to d_out.
//
// Measured optimum: 128 CTAs x 128 threads, one float4 per thread, regs=16,
// single wave across ~128 SMs. Duration is launch-overhead-bound
// (T_ovh ~5000 cyc + 1 DRAM round trip); DRAM at 0.8% of peak. Streaming
// store hint avoids L2 write-allocate bookkeeping on the (never re-read)
// output.

__global__ __launch_bounds__(128, 1)
void gcbf_copy_kernel(const float4* __restrict__ src, float4* __restrict__ dst) {
    int i = blockIdx.x * 128 + threadIdx.x;
    __stcs(dst + i, __ldg(src + i));
}

extern "C" void kernel_launch(void* const* d_in, const int* in_sizes, int n_in,
                              void* d_out, int out_size) {
    // inputs: [0] positions, [1] velocities, [2] obstacles, [3] raw_action
    gcbf_copy_kernel<<<128, 128>>>((const float4*)d_in[3], (float4*)d_out);
}